// round 15
// baseline (speedup 1.0000x reference)
#include <cuda_runtime.h>
#include <cuda_bf16.h>
#include <math.h>

#define NN 100000
#define EE 1600000
#define FIN 64
#define HID 16
#define CC 40
#define CAP 64              // slab capacity per node (P(deg>64) ~ 1e-18)
#define OFMAX 65536         // overflow list capacity (safety net)

typedef unsigned long long ull;

#define DEG_SCALE 33554432.0f   // 2^25 fixed-point for weighted degree
#define DEG_INV   (1.0f / 33554432.0f)

// ---------------- scratch (static device globals; no allocation) ----------------
__device__ ull   d_degcnt[NN + 1];    // [i<NN]: (cnt<<32)|fixed25(sum w); [NN].lo32 = overflow cnt
__device__ float d_dinv[NN];          // rsqrt(deg)
__device__ ull   d_slab[(size_t)NN * CAP];  // per-node edge slab: (src, w) packed
__device__ ull   d_osd[OFMAX];        // overflow: (src, w)
__device__ int   d_odst[OFMAX];       // overflow: dst
__device__ float d_z0[NN * HID];      // x @ W1[0]
__device__ float d_y1[NN * HID];      // x @ W1[1]; scaled in place to dinv*y1 by k_node
__device__ float d_h[NN * HID];       // relu(z0 - dinv*acc + b1)  (unscaled)
__device__ float d_hs[NN * HID];      // dinv * h (gather table for layer 2)

static ull*   p_degcnt;
static float* p_dinv;
static ull*   p_slab;
static ull*   p_osd;   static int* p_odst;  static int* p_ocnt;
static float* p_z0;    static float* p_y1;  static float* p_h;  static float* p_hs;
static cudaStream_t g_s2;
static cudaEvent_t  g_evA, g_evB;

// ---------------- kernels ----------------
// ONE edge pass: fused 64-bit atomic gives slot (hi32 ++) and accumulates
// fixed-point weighted degree (lo32). 2 edges/thread via int2/float2 loads.
__global__ void k_build(const int* __restrict__ ei, const float* __restrict__ w,
                        ull* degcnt, ull* slab, ull* osd, int* odst, int* ocnt,
                        int n2) {
    int t = blockIdx.x * blockDim.x + threadIdx.x;
    if (t >= n2) return;
    int2   ss = reinterpret_cast<const int2*>(ei)[t];        // src row
    int2   dd = reinterpret_cast<const int2*>(ei + EE)[t];   // dst row
    float2 ww = reinterpret_cast<const float2*>(w)[t];

    ull a0 = (1ULL << 32) | (ull)__float2uint_rn(ww.x * DEG_SCALE);
    ull old0 = atomicAdd(&degcnt[dd.x], a0);
    int slot0 = (int)(old0 >> 32);
    ull p0 = (ull)(unsigned)ss.x | ((ull)__float_as_uint(ww.x) << 32);
    if (slot0 < CAP) slab[(size_t)dd.x * CAP + slot0] = p0;
    else { int o = atomicAdd(ocnt, 1); if (o < OFMAX) { osd[o] = p0; odst[o] = dd.x; } }

    ull a1 = (1ULL << 32) | (ull)__float2uint_rn(ww.y * DEG_SCALE);
    ull old1 = atomicAdd(&degcnt[dd.y], a1);
    int slot1 = (int)(old1 >> 32);
    ull p1 = (ull)(unsigned)ss.y | ((ull)__float_as_uint(ww.y) << 32);
    if (slot1 < CAP) slab[(size_t)dd.y * CAP + slot1] = p1;
    else { int o = atomicAdd(ocnt, 1); if (o < OFMAX) { osd[o] = p1; odst[o] = dd.y; } }
}

// Per node: dinv = rsqrt(deg); y1 *= dinv (in place; gemm rewrites each replay).
__global__ void k_node(const ull* __restrict__ degcnt, float* dinv, float* y1, int n) {
    int i = blockIdx.x * blockDim.x + threadIdx.x;
    if (i >= n) return;
    float dg = (float)(unsigned)(degcnt[i] & 0xffffffffULL) * DEG_INV;
    float dv = (dg > 0.0f) ? rsqrtf(dg) : 0.0f;
    dinv[i] = dv;
    float4* y = reinterpret_cast<float4*>(y1 + (size_t)i * HID);
#pragma unroll
    for (int q = 0; q < HID / 4; q++) {
        float4 v = y[q];
        v.x *= dv; v.y *= dv; v.z *= dv; v.w *= dv;
        y[q] = v;
    }
}

// One projection: out = x @ Wsel (64x16). 16 accumulators/thread (~60 regs),
// 256-thread blocks -> high occupancy. Called twice on the side stream;
// second call reads x from L2 (25.6 MB < 126 MB L2).
__global__ void __launch_bounds__(256, 8)
k_gemmP(const float* __restrict__ x, const float* __restrict__ Wsel,
        float* outg, int n) {
    __shared__ float Ws[FIN * HID];
    for (int i = threadIdx.x; i < FIN * HID; i += blockDim.x)
        Ws[i] = Wsel[i];
    __syncthreads();
    int nd = blockIdx.x * blockDim.x + threadIdx.x;
    if (nd >= n) return;

    float acc[HID];
#pragma unroll
    for (int h = 0; h < HID; h++) acc[h] = 0.0f;

    const float4* xr = reinterpret_cast<const float4*>(x + (size_t)nd * FIN);
#pragma unroll
    for (int k4 = 0; k4 < FIN / 4; k4++) {
        float4 v = xr[k4];
        const float* wp = &Ws[(k4 * 4) * HID];
#pragma unroll
        for (int h = 0; h < HID; h++) {
            acc[h] += v.x * wp[h] + v.y * wp[HID + h] + v.z * wp[2 * HID + h] + v.w * wp[3 * HID + h];
        }
    }
    float4* o4 = reinterpret_cast<float4*>(outg + (size_t)nd * HID);
#pragma unroll
    for (int q = 0; q < HID / 4; q++)
        o4[q] = make_float4(acc[4 * q], acc[4 * q + 1], acc[4 * q + 2], acc[4 * q + 3]);
}

// Shared gather core: fixed-trip, fully-unrolled 32-edge chunks.
// Lanes with idx >= m load p=0 (src=0, w=0) so out-of-degree iterations
// contribute 0 via a cheap L1-resident load of tab[f]. MLP=16 per chunk.
__device__ __forceinline__ float gather_acc(
    const ull* __restrict__ slab, size_t sb, int m,
    const float* __restrict__ tab, int g, int f, int lane) {
    float acc = 0.0f;
    for (int c = 0; c < m; c += 32) {
        int idx = c + lane;
        ull p = (idx < m) ? slab[sb + idx] : 0ULL;
        int   srcl = (int)(unsigned)(p & 0xffffffffULL);
        float wl   = __uint_as_float((unsigned)(p >> 32));
#pragma unroll
        for (int j = 0; j < 16; j++) {
            int sl = 2 * j + g;
            int   src = __shfl_sync(0xffffffffu, srcl, sl);
            float wv  = __shfl_sync(0xffffffffu, wl, sl);
            acc += wv * __ldg(&tab[(size_t)src * HID + f]);
        }
    }
    return acc;
}

// Gather layer 1: warp per node over the node's slab.
// h = relu(z0 - dinv[nd]*acc + b1);  hs = dinv[nd]*h.
__global__ void __launch_bounds__(256, 8)
k_gather1(const ull* __restrict__ degcnt, const ull* __restrict__ slab,
          const ull* __restrict__ osd, const int* __restrict__ odst,
          const int* __restrict__ ocnt,
          const float* __restrict__ y1s, const float* __restrict__ z0,
          const float* __restrict__ b1, const float* __restrict__ dinv,
          float* __restrict__ h, float* __restrict__ hs, int n) {
    int warp = threadIdx.x >> 5;
    int lane = threadIdx.x & 31;
    int nd = blockIdx.x * 8 + warp;
    if (nd >= n) return;

    int cnt = (int)(degcnt[nd] >> 32);
    int m = cnt < CAP ? cnt : CAP;
    size_t sb = (size_t)nd * CAP;
    int g = lane >> 4, f = lane & 15;

    float acc = gather_acc(slab, sb, m, y1s, g, f, lane);
    acc += __shfl_xor_sync(0xffffffffu, acc, 16);

    if (g == 0) {
        if (cnt > CAP) {                              // ~never taken
            int oc = *ocnt; if (oc > OFMAX) oc = OFMAX;
            for (int i = 0; i < oc; i++) {
                if (odst[i] == nd) {
                    ull p = osd[i];
                    int src = (int)(unsigned)(p & 0xffffffffULL);
                    float wv = __uint_as_float((unsigned)(p >> 32));
                    acc += wv * y1s[(size_t)src * HID + f];
                }
            }
        }
        float dv = dinv[nd];
        float v = z0[(size_t)nd * HID + f] - dv * acc + __ldg(&b1[f]);
        v = fmaxf(v, 0.0f);
        h[(size_t)nd * HID + f] = v;
        hs[(size_t)nd * HID + f] = dv * v;
    }
}

// Gather layer 2 fused with final GEMM + log_softmax. Warp per node.
__global__ void __launch_bounds__(256, 8)
k_gather2_final(const ull* __restrict__ degcnt, const ull* __restrict__ slab,
                const ull* __restrict__ osd, const int* __restrict__ odst,
                const int* __restrict__ ocnt,
                const float* __restrict__ hsg, const float* __restrict__ hg,
                const float* __restrict__ dinv,
                const float* __restrict__ W2, const float* __restrict__ b2,
                float* __restrict__ out, int n) {
    __shared__ float W20s[HID * CC];
    __shared__ float W21s[HID * CC];
    __shared__ float b2s[CC];
    for (int i = threadIdx.x; i < HID * CC; i += blockDim.x) {
        W20s[i] = W2[i];
        W21s[i] = W2[HID * CC + i];
    }
    if (threadIdx.x < CC) b2s[threadIdx.x] = b2[threadIdx.x];
    __syncthreads();

    int warp = threadIdx.x >> 5;
    int lane = threadIdx.x & 31;
    int nd = blockIdx.x * 8 + warp;
    if (nd >= n) return;

    int cnt = (int)(degcnt[nd] >> 32);
    int m = cnt < CAP ? cnt : CAP;
    size_t sb = (size_t)nd * CAP;
    int g = lane >> 4, f = lane & 15;

    float acc = gather_acc(slab, sb, m, hsg, g, f, lane);
    acc += __shfl_xor_sync(0xffffffffu, acc, 16);
    if (g == 0 && cnt > CAP) {                        // ~never taken
        int oc = *ocnt; if (oc > OFMAX) oc = OFMAX;
        for (int i = 0; i < oc; i++) {
            if (odst[i] == nd) {
                ull p = osd[i];
                int src = (int)(unsigned)(p & 0xffffffffULL);
                float wv = __uint_as_float((unsigned)(p >> 32));
                acc += wv * hsg[(size_t)src * HID + f];
            }
        }
    }
    acc *= -dinv[nd];   // Tx1 feature f valid in lanes 0..15 (only ones read below)

    const float* hp = hg + (size_t)nd * HID;
    float oa = b2s[lane];                               // class = lane
    float ob = (lane < CC - 32) ? b2s[32 + lane] : 0.f; // class = lane+32
#pragma unroll
    for (int ff = 0; ff < HID; ff++) {
        float hf = hp[ff];                               // warp-uniform broadcast
        float af = __shfl_sync(0xffffffffu, acc, ff);    // lane ff holds feature ff
        oa += hf * W20s[ff * CC + lane] + af * W21s[ff * CC + lane];
        if (lane < CC - 32)
            ob += hf * W20s[ff * CC + 32 + lane] + af * W21s[ff * CC + 32 + lane];
    }

    float mx = (lane < CC - 32) ? fmaxf(oa, ob) : oa;
#pragma unroll
    for (int off = 16; off > 0; off >>= 1)
        mx = fmaxf(mx, __shfl_xor_sync(0xffffffffu, mx, off));

    float sexp = expf(oa - mx) + ((lane < CC - 32) ? expf(ob - mx) : 0.0f);
#pragma unroll
    for (int off = 16; off > 0; off >>= 1)
        sexp += __shfl_xor_sync(0xffffffffu, sexp, off);

    float lse = logf(sexp) + mx;

    float* op = out + (size_t)nd * CC;
    op[lane] = oa - lse;
    if (lane < CC - 32) op[32 + lane] = ob - lse;
}

// ---------------- prewarm ----------------
namespace {
struct Prewarm {
    Prewarm() {
        void* p;
        cudaGetSymbolAddress(&p, d_degcnt); p_degcnt = (ull*)p;
        cudaGetSymbolAddress(&p, d_dinv);   p_dinv   = (float*)p;
        cudaGetSymbolAddress(&p, d_slab);   p_slab   = (ull*)p;
        cudaGetSymbolAddress(&p, d_osd);    p_osd    = (ull*)p;
        cudaGetSymbolAddress(&p, d_odst);   p_odst   = (int*)p;
        cudaGetSymbolAddress(&p, d_z0);     p_z0     = (float*)p;
        cudaGetSymbolAddress(&p, d_y1);     p_y1     = (float*)p;
        cudaGetSymbolAddress(&p, d_h);      p_h      = (float*)p;
        cudaGetSymbolAddress(&p, d_hs);     p_hs     = (float*)p;
        p_ocnt = (int*)&p_degcnt[NN];       // overflow count lives in degcnt[NN].lo32

        cudaStreamCreateWithFlags(&g_s2, cudaStreamNonBlocking);
        cudaEventCreateWithFlags(&g_evA, cudaEventDisableTiming);
        cudaEventCreateWithFlags(&g_evB, cudaEventDisableTiming);

        // Degenerate launches to force module/code load + lmem pool sizing
        // before the harness checkpoint. All pointers valid; n=0 guards.
        const int*   di = (const int*)p_odst;
        const float* df = (const float*)p_z0;
        cudaMemsetAsync(p_degcnt, 0, (NN + 1) * sizeof(ull), 0);
        k_build<<<1, 32>>>(di, df, p_degcnt, p_slab, p_osd, p_odst, p_ocnt, 0);
        k_node<<<1, 32>>>(p_degcnt, p_dinv, p_y1, 0);
        k_gemmP<<<1, 256, 0, g_s2>>>(df, df, p_z0, 0);
        k_gather1<<<1, 256>>>(p_degcnt, p_slab, p_osd, p_odst, p_ocnt,
                              p_y1, p_z0, df, p_dinv, p_h, p_hs, 0);
        k_gather2_final<<<1, 256>>>(p_degcnt, p_slab, p_osd, p_odst, p_ocnt,
                                    p_hs, p_h, p_dinv, df, df, p_z0, 0);
        cudaDeviceSynchronize();
    }
};
Prewarm g_prewarm;
}  // namespace

// ---------------- launch ----------------
extern "C" void kernel_launch(void* const* d_in, const int* in_sizes, int n_in,
                              void* d_out, int out_size) {
    const float* x  = (const float*)d_in[0];
    const float* w  = (const float*)d_in[1];
    const float* W1 = (const float*)d_in[2];
    const float* b1 = (const float*)d_in[3];
    const float* W2 = (const float*)d_in[4];
    const float* b2 = (const float*)d_in[5];
    const int*   ei = (const int*)d_in[6];
    float* out = (float*)d_out;

    const int T = 256;

    // Fork: the two projections are fully independent -> side stream from t=0
    // (R14 linear experiment measured the fork worth ~11-15us).
    cudaEventRecord(g_evA, 0);
    cudaStreamWaitEvent(g_s2, g_evA, 0);
    k_gemmP<<<(NN + 255) / 256, 256, 0, g_s2>>>(x, W1, p_z0, NN);
    k_gemmP<<<(NN + 255) / 256, 256, 0, g_s2>>>(x, W1 + FIN * HID, p_y1, NN);
    cudaEventRecord(g_evB, g_s2);

    // Main chain: ONE edge pass builds slabs + weighted degrees.
    cudaMemsetAsync(p_degcnt, 0, (NN + 1) * sizeof(ull), 0);
    k_build<<<(EE / 2 + T - 1) / T, T>>>(ei, w, p_degcnt, p_slab, p_osd, p_odst, p_ocnt, EE / 2);

    // Join gemms, then per-node dinv + y1 scaling, then gathers.
    cudaStreamWaitEvent(0, g_evB, 0);
    k_node<<<(NN + T - 1) / T, T>>>(p_degcnt, p_dinv, p_y1, NN);
    k_gather1<<<(NN + 7) / 8, 256>>>(p_degcnt, p_slab, p_osd, p_odst, p_ocnt,
                                     p_y1, p_z0, b1, p_dinv, p_h, p_hs, NN);
    k_gather2_final<<<(NN + 7) / 8, 256>>>(p_degcnt, p_slab, p_osd, p_odst, p_ocnt,
                                           p_hs, p_h, p_dinv, W2, b2, out, NN);
}

// round 17
// speedup vs baseline: 1.3623x; 1.3623x over previous
#include <cuda_runtime.h>
#include <cuda_bf16.h>
#include <math.h>

#define NN 100000
#define EE 1600000
#define FIN 64
#define HID 16
#define CC 40
#define CAP 64              // slab capacity per node (P(deg>64) ~ 1e-18)
#define OFMAX 65536         // overflow list capacity (safety net)

typedef unsigned long long ull;

#define DEG_SCALE 33554432.0f   // 2^25 fixed-point for weighted degree
#define DEG_INV   (1.0f / 33554432.0f)

// ---------------- scratch (static device globals; no allocation) ----------------
__device__ ull   d_degcnt[NN];        // (cnt:int32 << 32) | fixed25(sum w)
__device__ float d_dinv[NN];          // rsqrt(deg)
__device__ ull   d_slab[(size_t)NN * CAP];  // per-node edge slab: (src, w) packed
__device__ ull   d_osd[OFMAX];        // overflow: (src, w)
__device__ int   d_odst[OFMAX];       // overflow: dst
__device__ int   d_ocnt[1];           // overflow count
__device__ float d_z0[NN * HID];      // x @ W1[0]
__device__ float d_y1[NN * HID];      // x @ W1[1]; scaled in place to dinv*y1 by k_node
__device__ float d_h[NN * HID];       // relu(z0 - dinv*acc + b1)  (unscaled)
__device__ float d_hs[NN * HID];      // dinv * h (gather table for layer 2)

static ull*   p_degcnt;
static float* p_dinv;
static ull*   p_slab;
static ull*   p_osd;   static int* p_odst;  static int* p_ocnt;
static float* p_z0;    static float* p_y1;  static float* p_h;  static float* p_hs;
static cudaStream_t g_s2;
static cudaEvent_t  g_evA, g_evB;

// ---------------- kernels ----------------
// ONE edge pass: fused 64-bit atomic gives slot (hi32 ++) and accumulates
// fixed-point weighted degree (lo32).
__global__ void k_build(const int* __restrict__ ei, const float* __restrict__ w,
                        ull* degcnt, ull* slab, ull* osd, int* odst, int* ocnt,
                        int n2) {
    int t = blockIdx.x * blockDim.x + threadIdx.x;
    if (t >= n2) return;
    int2   ss = reinterpret_cast<const int2*>(ei)[t];        // src row
    int2   dd = reinterpret_cast<const int2*>(ei + EE)[t];   // dst row
    float2 ww = reinterpret_cast<const float2*>(w)[t];

    ull a0 = (1ULL << 32) | (ull)__float2uint_rn(ww.x * DEG_SCALE);
    ull old0 = atomicAdd(&degcnt[dd.x], a0);
    int slot0 = (int)(old0 >> 32);
    ull p0 = (ull)(unsigned)ss.x | ((ull)__float_as_uint(ww.x) << 32);
    if (slot0 < CAP) slab[(size_t)dd.x * CAP + slot0] = p0;
    else { int o = atomicAdd(ocnt, 1); if (o < OFMAX) { osd[o] = p0; odst[o] = dd.x; } }

    ull a1 = (1ULL << 32) | (ull)__float2uint_rn(ww.y * DEG_SCALE);
    ull old1 = atomicAdd(&degcnt[dd.y], a1);
    int slot1 = (int)(old1 >> 32);
    ull p1 = (ull)(unsigned)ss.y | ((ull)__float_as_uint(ww.y) << 32);
    if (slot1 < CAP) slab[(size_t)dd.y * CAP + slot1] = p1;
    else { int o = atomicAdd(ocnt, 1); if (o < OFMAX) { osd[o] = p1; odst[o] = dd.y; } }
}

// Per node: dinv = rsqrt(deg); y1 *= dinv (in place; gemm1 rewrites each replay).
__global__ void k_node(const ull* __restrict__ degcnt, float* dinv, float* y1, int n) {
    int i = blockIdx.x * blockDim.x + threadIdx.x;
    if (i >= n) return;
    float dg = (float)(unsigned)(degcnt[i] & 0xffffffffULL) * DEG_INV;
    float dv = (dg > 0.0f) ? rsqrtf(dg) : 0.0f;
    dinv[i] = dv;
    float4* y = reinterpret_cast<float4*>(y1 + (size_t)i * HID);
#pragma unroll
    for (int q = 0; q < HID / 4; q++) {
        float4 v = y[q];
        v.x *= dv; v.y *= dv; v.z *= dv; v.w *= dv;
        y[q] = v;
    }
}

// z0 = x@W1[0], y1 = x@W1[1], fused (reads x once). Fully independent ->
// forked on side stream at t=0, hidden under the structure chain.
__global__ void __launch_bounds__(128, 1)
k_gemm1(const float* __restrict__ x, const float* __restrict__ W1,
        float* z0g, float* y1g, int n) {
    __shared__ float W0s[FIN * HID];
    __shared__ float W1s[FIN * HID];
    for (int i = threadIdx.x; i < FIN * HID; i += blockDim.x) {
        W0s[i] = W1[i];
        W1s[i] = W1[FIN * HID + i];
    }
    __syncthreads();
    int nd = blockIdx.x * blockDim.x + threadIdx.x;
    if (nd >= n) return;

    float acc0[HID], acc1[HID];
#pragma unroll
    for (int h = 0; h < HID; h++) { acc0[h] = 0.0f; acc1[h] = 0.0f; }

    const float4* xr = reinterpret_cast<const float4*>(x + (size_t)nd * FIN);
#pragma unroll
    for (int k4 = 0; k4 < FIN / 4; k4++) {
        float4 v = xr[k4];
        const float* w0 = &W0s[(k4 * 4) * HID];
        const float* w1 = &W1s[(k4 * 4) * HID];
#pragma unroll
        for (int h = 0; h < HID; h++) {
            acc0[h] += v.x * w0[h] + v.y * w0[HID + h] + v.z * w0[2 * HID + h] + v.w * w0[3 * HID + h];
            acc1[h] += v.x * w1[h] + v.y * w1[HID + h] + v.z * w1[2 * HID + h] + v.w * w1[3 * HID + h];
        }
    }
    float4* z0 = reinterpret_cast<float4*>(z0g + (size_t)nd * HID);
    float4* y1 = reinterpret_cast<float4*>(y1g + (size_t)nd * HID);
#pragma unroll
    for (int q = 0; q < HID / 4; q++) {
        z0[q] = make_float4(acc0[4 * q], acc0[4 * q + 1], acc0[4 * q + 2], acc0[4 * q + 3]);
        y1[q] = make_float4(acc1[4 * q], acc1[4 * q + 1], acc1[4 * q + 2], acc1[4 * q + 3]);
    }
}

// Gather layer 1: warp per node over the node's slab. Coalesced slab fetch
// (one edge per lane), shuffle-broadcast (src,w); 16-lane group g handles
// edges 2j+g; lane's feature f = lane&15. unroll 8 = full batch for deg<=16
// chunks (jmax ~ 8) -> MLP ~8 on the table loads.
// h = relu(z0 - dinv[nd]*acc + b1);  hs = dinv[nd]*h.
__global__ void __launch_bounds__(256, 8)
k_gather1(const ull* __restrict__ degcnt, const ull* __restrict__ slab,
          const ull* __restrict__ osd, const int* __restrict__ odst,
          const int* __restrict__ ocnt,
          const float* __restrict__ y1s, const float* __restrict__ z0,
          const float* __restrict__ b1, const float* __restrict__ dinv,
          float* __restrict__ h, float* __restrict__ hs, int n) {
    int warp = threadIdx.x >> 5;
    int lane = threadIdx.x & 31;
    int nd = blockIdx.x * 8 + warp;
    if (nd >= n) return;

    int cnt = (int)(degcnt[nd] >> 32);
    int m = cnt < CAP ? cnt : CAP;
    size_t sb = (size_t)nd * CAP;
    int g = lane >> 4, f = lane & 15;

    float acc = 0.0f;
    for (int c = 0; c < m; c += 32) {
        int idx = c + lane;
        ull p = (idx < m) ? slab[sb + idx] : 0ULL;   // OOB -> src=0, w=0
        int   srcl = (int)(unsigned)(p & 0xffffffffULL);
        float wl   = __uint_as_float((unsigned)(p >> 32));
        int rem = m - c; if (rem > 32) rem = 32;
        int jmax = (rem + 1) >> 1;                   // warp-uniform
#pragma unroll 8
        for (int j = 0; j < jmax; j++) {
            int sl = 2 * j + g;
            int   src = __shfl_sync(0xffffffffu, srcl, sl);
            float wv  = __shfl_sync(0xffffffffu, wl, sl);
            acc += wv * __ldg(&y1s[(size_t)src * HID + f]);
        }
    }
    acc += __shfl_xor_sync(0xffffffffu, acc, 16);

    if (g == 0) {
        if (cnt > CAP) {                              // ~never taken
            int oc = *ocnt; if (oc > OFMAX) oc = OFMAX;
            for (int i = 0; i < oc; i++) {
                if (odst[i] == nd) {
                    ull p = osd[i];
                    int src = (int)(unsigned)(p & 0xffffffffULL);
                    float wv = __uint_as_float((unsigned)(p >> 32));
                    acc += wv * y1s[(size_t)src * HID + f];
                }
            }
        }
        float dv = dinv[nd];
        float v = z0[(size_t)nd * HID + f] - dv * acc + __ldg(&b1[f]);
        v = fmaxf(v, 0.0f);
        h[(size_t)nd * HID + f] = v;
        hs[(size_t)nd * HID + f] = dv * v;
    }
}

// Gather layer 2 fused with final GEMM + log_softmax. Warp per node.
__global__ void __launch_bounds__(256, 8)
k_gather2_final(const ull* __restrict__ degcnt, const ull* __restrict__ slab,
                const ull* __restrict__ osd, const int* __restrict__ odst,
                const int* __restrict__ ocnt,
                const float* __restrict__ hsg, const float* __restrict__ hg,
                const float* __restrict__ dinv,
                const float* __restrict__ W2, const float* __restrict__ b2,
                float* __restrict__ out, int n) {
    __shared__ float W20s[HID * CC];
    __shared__ float W21s[HID * CC];
    __shared__ float b2s[CC];
    for (int i = threadIdx.x; i < HID * CC; i += blockDim.x) {
        W20s[i] = W2[i];
        W21s[i] = W2[HID * CC + i];
    }
    if (threadIdx.x < CC) b2s[threadIdx.x] = b2[threadIdx.x];
    __syncthreads();

    int warp = threadIdx.x >> 5;
    int lane = threadIdx.x & 31;
    int nd = blockIdx.x * 8 + warp;
    if (nd >= n) return;

    int cnt = (int)(degcnt[nd] >> 32);
    int m = cnt < CAP ? cnt : CAP;
    size_t sb = (size_t)nd * CAP;
    int g = lane >> 4, f = lane & 15;

    float acc = 0.0f;
    for (int c = 0; c < m; c += 32) {
        int idx = c + lane;
        ull p = (idx < m) ? slab[sb + idx] : 0ULL;
        int   srcl = (int)(unsigned)(p & 0xffffffffULL);
        float wl   = __uint_as_float((unsigned)(p >> 32));
        int rem = m - c; if (rem > 32) rem = 32;
        int jmax = (rem + 1) >> 1;
#pragma unroll 8
        for (int j = 0; j < jmax; j++) {
            int sl = 2 * j + g;
            int   src = __shfl_sync(0xffffffffu, srcl, sl);
            float wv  = __shfl_sync(0xffffffffu, wl, sl);
            acc += wv * __ldg(&hsg[(size_t)src * HID + f]);
        }
    }
    acc += __shfl_xor_sync(0xffffffffu, acc, 16);
    if (g == 0 && cnt > CAP) {                        // ~never taken
        int oc = *ocnt; if (oc > OFMAX) oc = OFMAX;
        for (int i = 0; i < oc; i++) {
            if (odst[i] == nd) {
                ull p = osd[i];
                int src = (int)(unsigned)(p & 0xffffffffULL);
                float wv = __uint_as_float((unsigned)(p >> 32));
                acc += wv * hsg[(size_t)src * HID + f];
            }
        }
    }
    acc *= -dinv[nd];   // Tx1 feature f valid in lanes 0..15 (only ones read below)

    const float* hp = hg + (size_t)nd * HID;
    float oa = b2s[lane];                               // class = lane
    float ob = (lane < CC - 32) ? b2s[32 + lane] : 0.f; // class = lane+32
#pragma unroll
    for (int ff = 0; ff < HID; ff++) {
        float hf = hp[ff];                               // warp-uniform broadcast
        float af = __shfl_sync(0xffffffffu, acc, ff);    // lane ff holds feature ff
        oa += hf * W20s[ff * CC + lane] + af * W21s[ff * CC + lane];
        if (lane < CC - 32)
            ob += hf * W20s[ff * CC + 32 + lane] + af * W21s[ff * CC + 32 + lane];
    }

    float mx = (lane < CC - 32) ? fmaxf(oa, ob) : oa;
#pragma unroll
    for (int off = 16; off > 0; off >>= 1)
        mx = fmaxf(mx, __shfl_xor_sync(0xffffffffu, mx, off));

    float sexp = expf(oa - mx) + ((lane < CC - 32) ? expf(ob - mx) : 0.0f);
#pragma unroll
    for (int off = 16; off > 0; off >>= 1)
        sexp += __shfl_xor_sync(0xffffffffu, sexp, off);

    float lse = logf(sexp) + mx;

    float* op = out + (size_t)nd * CC;
    op[lane] = oa - lse;
    if (lane < CC - 32) op[32 + lane] = ob - lse;
}

// ---------------- prewarm ----------------
namespace {
struct Prewarm {
    Prewarm() {
        void* p;
        cudaGetSymbolAddress(&p, d_degcnt); p_degcnt = (ull*)p;
        cudaGetSymbolAddress(&p, d_dinv);   p_dinv   = (float*)p;
        cudaGetSymbolAddress(&p, d_slab);   p_slab   = (ull*)p;
        cudaGetSymbolAddress(&p, d_osd);    p_osd    = (ull*)p;
        cudaGetSymbolAddress(&p, d_odst);   p_odst   = (int*)p;
        cudaGetSymbolAddress(&p, d_ocnt);   p_ocnt   = (int*)p;
        cudaGetSymbolAddress(&p, d_z0);     p_z0     = (float*)p;
        cudaGetSymbolAddress(&p, d_y1);     p_y1     = (float*)p;
        cudaGetSymbolAddress(&p, d_h);      p_h      = (float*)p;
        cudaGetSymbolAddress(&p, d_hs);     p_hs     = (float*)p;

        cudaStreamCreateWithFlags(&g_s2, cudaStreamNonBlocking);
        cudaEventCreateWithFlags(&g_evA, cudaEventDisableTiming);
        cudaEventCreateWithFlags(&g_evB, cudaEventDisableTiming);

        // Degenerate launches to force module/code load + lmem pool sizing
        // before the harness checkpoint. All pointers valid; n=0 guards.
        const int*   di = (const int*)p_odst;
        const float* df = (const float*)p_z0;
        cudaMemsetAsync(p_degcnt, 0, NN * sizeof(ull), 0);
        cudaMemsetAsync(p_ocnt, 0, sizeof(int), 0);
        k_build<<<1, 32>>>(di, df, p_degcnt, p_slab, p_osd, p_odst, p_ocnt, 0);
        k_node<<<1, 32>>>(p_degcnt, p_dinv, p_y1, 0);
        k_gemm1<<<1, 128, 0, g_s2>>>(df, df, p_z0, p_y1, 0);
        k_gather1<<<1, 256>>>(p_degcnt, p_slab, p_osd, p_odst, p_ocnt,
                              p_y1, p_z0, df, p_dinv, p_h, p_hs, 0);
        k_gather2_final<<<1, 256>>>(p_degcnt, p_slab, p_osd, p_odst, p_ocnt,
                                    p_hs, p_h, p_dinv, df, df, p_z0, 0);
        cudaDeviceSynchronize();
    }
};
Prewarm g_prewarm;
}  // namespace

// ---------------- launch ----------------
extern "C" void kernel_launch(void* const* d_in, const int* in_sizes, int n_in,
                              void* d_out, int out_size) {
    const float* x  = (const float*)d_in[0];
    const float* w  = (const float*)d_in[1];
    const float* W1 = (const float*)d_in[2];
    const float* b1 = (const float*)d_in[3];
    const float* W2 = (const float*)d_in[4];
    const float* b2 = (const float*)d_in[5];
    const int*   ei = (const int*)d_in[6];
    float* out = (float*)d_out;

    const int T = 256;

    // Fork: gemm1 is fully independent -> side stream from t=0.
    cudaEventRecord(g_evA, 0);
    cudaStreamWaitEvent(g_s2, g_evA, 0);
    k_gemm1<<<(NN + 127) / 128, 128, 0, g_s2>>>(x, W1, p_z0, p_y1, NN);
    cudaEventRecord(g_evB, g_s2);

    // Main chain: ONE edge pass builds slabs + weighted degrees.
    cudaMemsetAsync(p_degcnt, 0, NN * sizeof(ull), 0);
    cudaMemsetAsync(p_ocnt, 0, sizeof(int), 0);
    k_build<<<(EE / 2 + T - 1) / T, T>>>(ei, w, p_degcnt, p_slab, p_osd, p_odst, p_ocnt, EE / 2);

    // Join gemm1, then per-node dinv + y1 scaling, then gathers.
    cudaStreamWaitEvent(0, g_evB, 0);
    k_node<<<(NN + T - 1) / T, T>>>(p_degcnt, p_dinv, p_y1, NN);
    k_gather1<<<(NN + 7) / 8, 256>>>(p_degcnt, p_slab, p_osd, p_odst, p_ocnt,
                                     p_y1, p_z0, b1, p_dinv, p_h, p_hs, NN);
    k_gather2_final<<<(NN + 7) / 8, 256>>>(p_degcnt, p_slab, p_osd, p_odst, p_ocnt,
                                           p_hs, p_h, p_dinv, W2, b2, out, NN);
}